// round 6
// baseline (speedup 1.0000x reference)
#include <cuda_runtime.h>
#include <cuda_fp16.h>
#include <math.h>

// ---------------------------------------------------------------------------
// MultiScaleCrossAttn — fp16 MMA GEMMs + fused proj/LN/FF chain kernel
// ---------------------------------------------------------------------------

#define ROWS0 12544      // 64*14*14
#define ROWS1 200704     // 64*56*56
#define ROWS2 65536      // 64*32*32
#define KVROWS 313600    // 64*196*25

__device__ float g_t0[ROWS0 * 96];
__device__ float g_t1[ROWS1 * 96];
__device__ float g_t2[ROWS2 * 96];
__device__ __align__(16) __half g_qkv[ROWS1 * 288];
__device__ __align__(16) __half g_ob[ROWS1 * 96];
__device__ __align__(16) __half g_kv[KVROWS * 96];
__device__ __align__(16) __half g_k[KVROWS * 96];
__device__ __align__(16) __half g_v[KVROWS * 96];
__device__ __align__(16) __half g_q[ROWS0 * 96];
__device__ __align__(16) __half g_co[ROWS0 * 96];

static constexpr int AS_U4 = 6 * 8 * 32;   // 24KB
static constexpr int BS_U4 = 6 * 6 * 32;   // 18KB
static constexpr int TF_LD = 100;          // fp32 row pitch in resff smem
static constexpr int RES_SMEM = (128 * TF_LD) * 4 + AS_U4 * 16 + BS_U4 * 16;  // 94208

__device__ __forceinline__ unsigned f2h2(float lo, float hi) {
    __half2 h = __floats2half2_rn(lo, hi);
    return *reinterpret_cast<unsigned*>(&h);
}

__device__ __forceinline__ void mma16(float c[4], uint4 a, unsigned b0, unsigned b1) {
    asm volatile(
        "mma.sync.aligned.m16n8k16.row.col.f32.f16.f16.f32 "
        "{%0,%1,%2,%3}, {%4,%5,%6,%7}, {%8,%9}, {%0,%1,%2,%3};\n"
        : "+f"(c[0]), "+f"(c[1]), "+f"(c[2]), "+f"(c[3])
        : "r"(a.x), "r"(a.y), "r"(a.z), "r"(a.w), "r"(b0), "r"(b1));
}

__device__ __forceinline__ float gelu_f(float v) {
    return 0.5f * v * (1.f + erff(v * 0.70710678118654752f));
}

// zeroes acc and runs the 6x12 MMA mainloop
__device__ __forceinline__ void gemm_main(float acc[2][6][4], const uint4* As4,
                                          const uint4* Bs4, int mg, int nh, int lane) {
#pragma unroll
    for (int m = 0; m < 2; ++m)
#pragma unroll
        for (int j = 0; j < 6; ++j)
#pragma unroll
            for (int i = 0; i < 4; ++i) acc[m][j][i] = 0.f;
#pragma unroll
    for (int kt = 0; kt < 6; ++kt) {
        uint4 a0 = As4[(kt * 8 + mg * 2) * 32 + lane];
        uint4 a1 = As4[(kt * 8 + mg * 2 + 1) * 32 + lane];
        uint4 b0 = Bs4[(kt * 6 + nh * 3) * 32 + lane];
        uint4 b1 = Bs4[(kt * 6 + nh * 3 + 1) * 32 + lane];
        uint4 b2 = Bs4[(kt * 6 + nh * 3 + 2) * 32 + lane];
        mma16(acc[0][0], a0, b0.x, b0.y); mma16(acc[0][1], a0, b0.z, b0.w);
        mma16(acc[0][2], a0, b1.x, b1.y); mma16(acc[0][3], a0, b1.z, b1.w);
        mma16(acc[0][4], a0, b2.x, b2.y); mma16(acc[0][5], a0, b2.z, b2.w);
        mma16(acc[1][0], a1, b0.x, b0.y); mma16(acc[1][1], a1, b0.z, b0.w);
        mma16(acc[1][2], a1, b1.x, b1.y); mma16(acc[1][3], a1, b1.z, b1.w);
        mma16(acc[1][4], a1, b2.x, b2.y); mma16(acc[1][5], a1, b2.z, b2.w);
    }
}

// stage a 96x96 fp32 weight slice into fp16 frag-order smem
__device__ __forceinline__ void stage_B(unsigned* Bs, const float* W, int ldw,
                                        int ncol0, int tid) {
    for (int idx = tid; idx < BS_U4 * 4; idx += 256) {
        int kt = idx / 768;
        int r = idx - kt * 768;
        int jp = r >> 7;
        int r2 = r & 127;
        int ln = r2 >> 2, c = r2 & 3;
        int tig = ln & 3, gid = ln >> 2;
        int n = ncol0 + ((jp << 1) + (c >> 1)) * 8 + gid;
        int k = kt * 16 + 2 * tig + ((c & 1) << 3);
        Bs[idx] = f2h2(__ldg(&W[k * ldw + n]), __ldg(&W[(k + 1) * ldw + n]));
    }
}

// ---------------------------------------------------------------------------
// generic GEMM (qkv / q-proj / dual kv-proj). Same as R5.
// ---------------------------------------------------------------------------
template <class TA, class TO, bool LNF, bool GELU, int EPI, bool DUAL>
__global__ __launch_bounds__(256, 3) void gemm_tc(const TA* __restrict__ A,
                                                  const float* __restrict__ W,
                                                  const float* __restrict__ W2,
                                                  const float* __restrict__ bias,
                                                  const float* __restrict__ lng,
                                                  const float* __restrict__ lnb,
                                                  const float* __restrict__ res,
                                                  TO* __restrict__ out,
                                                  TO* __restrict__ out2, int ldw) {
    constexpr bool TAH = (sizeof(TA) == 2);
    constexpr bool TOH = (sizeof(TO) == 2);
    __shared__ uint4 As4[AS_U4];
    __shared__ uint4 Bs4[BS_U4];
    unsigned* As = (unsigned*)As4;
    unsigned* Bs = (unsigned*)Bs4;
    const int tid = threadIdx.x, lane = tid & 31, warp = tid >> 5;
    const int row0 = blockIdx.x * 128;
    int ncol0 = 0;
    if (DUAL) {
        if (blockIdx.y) { W = W2; out = out2; }
    } else {
        ncol0 = blockIdx.y * 96;
    }

    stage_B(Bs, W, ldw, ncol0, tid);

    {
        const int row = tid >> 1, sub = tid & 1;
        const int mt = row >> 4, r16 = row & 15;
        const int gid8 = r16 & 7, rowhi = r16 >> 3;
        if constexpr (TAH) {
            const uint4* ap = (const uint4*)((const __half*)A + (size_t)(row0 + row) * 96 + sub * 48);
#pragma unroll
            for (int j = 0; j < 6; ++j) {
                uint4 u = __ldg(&ap[j]);
                unsigned w[4] = {u.x, u.y, u.z, u.w};
#pragma unroll
                for (int wi = 0; wi < 4; ++wi) {
                    int P = sub * 24 + j * 4 + wi;
                    int kt = P >> 3, hi = (P >> 2) & 1, tg = P & 3;
                    As[(((kt * 8 + mt) * 32) + (gid8 << 2) + tg) * 4 + (rowhi | (hi << 1))] = w[wi];
                }
            }
        } else {
            const float* ap = (const float*)A + (size_t)(row0 + row) * 96 + sub * 48;
            float4 vals[12];
#pragma unroll
            for (int j = 0; j < 12; ++j) vals[j] = __ldg((const float4*)(ap + j * 4));
            float mean = 0.f, rstd = 0.f;
            if (LNF) {
                float s = 0.f, s2 = 0.f;
#pragma unroll
                for (int j = 0; j < 12; ++j) {
                    float4 v = vals[j];
                    s += v.x + v.y + v.z + v.w;
                    s2 += v.x * v.x + v.y * v.y + v.z * v.z + v.w * v.w;
                }
                s += __shfl_xor_sync(0xffffffffu, s, 1);
                s2 += __shfl_xor_sync(0xffffffffu, s2, 1);
                mean = s * (1.f / 96.f);
                float var = fmaf(-mean, mean, s2 * (1.f / 96.f));
                rstd = rsqrtf(var + 1e-5f);
            }
#pragma unroll
            for (int j = 0; j < 12; ++j) {
                int k0 = sub * 48 + j * 4;
                float4 v = vals[j];
                if (LNF) {
                    float4 g = __ldg((const float4*)(lng + k0));
                    float4 bb = __ldg((const float4*)(lnb + k0));
                    v.x = (v.x - mean) * rstd * g.x + bb.x;
                    v.y = (v.y - mean) * rstd * g.y + bb.y;
                    v.z = (v.z - mean) * rstd * g.z + bb.z;
                    v.w = (v.w - mean) * rstd * g.w + bb.w;
                }
                int kt = k0 >> 4, kk = k0 & 15;
                int hi = kk >> 3, tig = (kk & 7) >> 1;
                unsigned base = (((kt * 8 + mt) * 32) + (gid8 << 2) + tig) * 4;
                As[base + (rowhi | (hi << 1))] = f2h2(v.x, v.y);
                As[base + 4 + (rowhi | (hi << 1))] = f2h2(v.z, v.w);
            }
        }
    }
    __syncthreads();

    const int mg = warp & 3, nh = warp >> 2;
    float acc[2][6][4];
    gemm_main(acc, As4, Bs4, mg, nh, lane);

    const int gid = lane >> 2, tig = lane & 3;
#pragma unroll
    for (int m = 0; m < 2; ++m) {
        int rr = row0 + (mg * 2 + m) * 16 + gid;
#pragma unroll
        for (int j = 0; j < 6; ++j) {
            int nc = ncol0 + (nh * 6 + j) * 8 + tig * 2;
            float bx = 0.f, by = 0.f;
            if (bias) {
                float2 bv = *(const float2*)&bias[nc];
                bx = bv.x; by = bv.y;
            }
            float x0 = acc[m][j][0] + bx, x1 = acc[m][j][1] + by;
            float x2 = acc[m][j][2] + bx, x3 = acc[m][j][3] + by;
            if (GELU) { x0 = gelu_f(x0); x1 = gelu_f(x1); x2 = gelu_f(x2); x3 = gelu_f(x3); }
            if constexpr (TOH) {
                __half2* p0 = (__half2*)((__half*)out + (size_t)rr * ldw + nc);
                __half2* p1 = (__half2*)((__half*)out + (size_t)(rr + 8) * ldw + nc);
                *p0 = __floats2half2_rn(x0, x1);
                *p1 = __floats2half2_rn(x2, x3);
            } else {
                float* p0 = (float*)out + (size_t)rr * ldw + nc;
                float* p1 = (float*)out + (size_t)(rr + 8) * ldw + nc;
                if constexpr (EPI == 0) {
                    *(float2*)p0 = make_float2(x0, x1);
                    *(float2*)p1 = make_float2(x2, x3);
                } else if constexpr (EPI == 1) {
                    float2 o0 = *(float2*)p0, o1 = *(float2*)p1;
                    *(float2*)p0 = make_float2(o0.x + x0, o0.y + x1);
                    *(float2*)p1 = make_float2(o1.x + x2, o1.y + x3);
                } else {
                    float2 r0 = *(const float2*)&res[(size_t)rr * 96 + nc];
                    float2 r1 = *(const float2*)&res[(size_t)(rr + 8) * 96 + nc];
                    *(float2*)p0 = make_float2(r0.x + x0, r0.y + x1);
                    *(float2*)p1 = make_float2(r1.x + x2, r1.y + x3);
                }
            }
        }
    }
}

// ---------------------------------------------------------------------------
// FUSED: tnew = tin + ob@Wo + bo ;  tout = tnew + gelu(LN(tnew)@W1+b1)@W2 + b2
// One 128-row tile, 3 chained GEMMs, tnew lives in smem.
// ---------------------------------------------------------------------------
__global__ __launch_bounds__(256) void resff_tc(const __half* __restrict__ ob,
                                                const float* __restrict__ tin,
                                                float* __restrict__ tout,
                                                const float* __restrict__ Wo,
                                                const float* __restrict__ bo,
                                                const float* __restrict__ lng,
                                                const float* __restrict__ lnb,
                                                const float* __restrict__ W1,
                                                const float* __restrict__ b1,
                                                const float* __restrict__ W2,
                                                const float* __restrict__ b2) {
    extern __shared__ float dyn[];
    float* Tf = dyn;                                   // [128][TF_LD]
    unsigned* As = (unsigned*)(dyn + 128 * TF_LD);
    unsigned* Bs = As + AS_U4 * 4;
    uint4* As4 = (uint4*)As;
    uint4* Bs4 = (uint4*)Bs;
    const int tid = threadIdx.x, lane = tid & 31, warp = tid >> 5;
    const int row0 = blockIdx.x * 128;
    const int mg = warp & 3, nh = warp >> 2;
    const int gid = lane >> 2, tig = lane & 3;
    float acc[2][6][4];

    // ---- phase 1: stage ob (fp16 repack) + Wo ----
    {
        const int row = tid >> 1, sub = tid & 1;
        const int mt = row >> 4, r16 = row & 15;
        const int gid8 = r16 & 7, rowhi = r16 >> 3;
        const uint4* ap = (const uint4*)(ob + (size_t)(row0 + row) * 96 + sub * 48);
#pragma unroll
        for (int j = 0; j < 6; ++j) {
            uint4 u = __ldg(&ap[j]);
            unsigned w[4] = {u.x, u.y, u.z, u.w};
#pragma unroll
            for (int wi = 0; wi < 4; ++wi) {
                int P = sub * 24 + j * 4 + wi;
                int kt = P >> 3, hi = (P >> 2) & 1, tg = P & 3;
                As[(((kt * 8 + mt) * 32) + (gid8 << 2) + tg) * 4 + (rowhi | (hi << 1))] = w[wi];
            }
        }
    }
    stage_B(Bs, Wo, 96, 0, tid);
    __syncthreads();

    gemm_main(acc, As4, Bs4, mg, nh, lane);

    // tnew = acc + bo + tin  -> Tf (smem)
#pragma unroll
    for (int m = 0; m < 2; ++m) {
        int rl = (mg * 2 + m) * 16 + gid;
#pragma unroll
        for (int j = 0; j < 6; ++j) {
            int nc = (nh * 6 + j) * 8 + tig * 2;
            float2 bv = *(const float2*)&bo[nc];
            float2 r0 = *(const float2*)&tin[(size_t)(row0 + rl) * 96 + nc];
            float2 r1 = *(const float2*)&tin[(size_t)(row0 + rl + 8) * 96 + nc];
            *(float2*)&Tf[rl * TF_LD + nc] =
                make_float2(acc[m][j][0] + bv.x + r0.x, acc[m][j][1] + bv.y + r0.y);
            *(float2*)&Tf[(rl + 8) * TF_LD + nc] =
                make_float2(acc[m][j][2] + bv.x + r1.x, acc[m][j][3] + bv.y + r1.y);
        }
    }
    __syncthreads();

    // ---- phase 2: LN(Tf) -> As ; W1 -> Bs ----
    {
        const int row = tid >> 1, sub = tid & 1;
        const int mt = row >> 4, r16 = row & 15;
        const int gid8 = r16 & 7, rowhi = r16 >> 3;
        const float* ap = Tf + row * TF_LD + sub * 48;
        float4 vals[12];
#pragma unroll
        for (int j = 0; j < 12; ++j) vals[j] = *(const float4*)(ap + j * 4);
        float s = 0.f, s2 = 0.f;
#pragma unroll
        for (int j = 0; j < 12; ++j) {
            float4 v = vals[j];
            s += v.x + v.y + v.z + v.w;
            s2 += v.x * v.x + v.y * v.y + v.z * v.z + v.w * v.w;
        }
        s += __shfl_xor_sync(0xffffffffu, s, 1);
        s2 += __shfl_xor_sync(0xffffffffu, s2, 1);
        float mean = s * (1.f / 96.f);
        float var = fmaf(-mean, mean, s2 * (1.f / 96.f));
        float rstd = rsqrtf(var + 1e-5f);
#pragma unroll
        for (int j = 0; j < 12; ++j) {
            int k0 = sub * 48 + j * 4;
            float4 v = vals[j];
            float4 g = __ldg((const float4*)(lng + k0));
            float4 bb = __ldg((const float4*)(lnb + k0));
            v.x = (v.x - mean) * rstd * g.x + bb.x;
            v.y = (v.y - mean) * rstd * g.y + bb.y;
            v.z = (v.z - mean) * rstd * g.z + bb.z;
            v.w = (v.w - mean) * rstd * g.w + bb.w;
            int kt = k0 >> 4, kk = k0 & 15;
            int hi = kk >> 3, tg = (kk & 7) >> 1;
            unsigned base = (((kt * 8 + mt) * 32) + (gid8 << 2) + tg) * 4;
            As[base + (rowhi | (hi << 1))] = f2h2(v.x, v.y);
            As[base + 4 + (rowhi | (hi << 1))] = f2h2(v.z, v.w);
        }
    }
    stage_B(Bs, W1, 96, 0, tid);
    __syncthreads();

    gemm_main(acc, As4, Bs4, mg, nh, lane);
    __syncthreads();  // all GEMM2 reads of As/Bs done before overwrite

    // ---- phase 3: h = gelu(acc + b1) -> As (direct C->A frag mapping); W2 -> Bs
#pragma unroll
    for (int m = 0; m < 2; ++m) {
        int mt2 = mg * 2 + m;
#pragma unroll
        for (int j = 0; j < 6; ++j) {
            int col8 = nh * 6 + j;          // output 8-col group = k-group of h
            int kt = col8 >> 1, hi = col8 & 1;
            int k0 = col8 * 8 + tig * 2;
            float2 bv = *(const float2*)&b1[k0];
            float x0 = gelu_f(acc[m][j][0] + bv.x), x1 = gelu_f(acc[m][j][1] + bv.y);
            float x2 = gelu_f(acc[m][j][2] + bv.x), x3 = gelu_f(acc[m][j][3] + bv.y);
            unsigned base = (((kt * 8 + mt2) * 32) + (gid << 2) + tig) * 4;
            As[base + (hi << 1)] = f2h2(x0, x1);
            As[base + 1 + (hi << 1)] = f2h2(x2, x3);
        }
    }
    stage_B(Bs, W2, 96, 0, tid);
    __syncthreads();

    gemm_main(acc, As4, Bs4, mg, nh, lane);

    // tout = Tf + acc + b2
#pragma unroll
    for (int m = 0; m < 2; ++m) {
        int rl = (mg * 2 + m) * 16 + gid;
#pragma unroll
        for (int j = 0; j < 6; ++j) {
            int nc = (nh * 6 + j) * 8 + tig * 2;
            float2 bv = *(const float2*)&b2[nc];
            float2 t0v = *(const float2*)&Tf[rl * TF_LD + nc];
            float2 t1v = *(const float2*)&Tf[(rl + 8) * TF_LD + nc];
            *(float2*)&tout[(size_t)(row0 + rl) * 96 + nc] =
                make_float2(acc[m][j][0] + bv.x + t0v.x, acc[m][j][1] + bv.y + t0v.y);
            *(float2*)&tout[(size_t)(row0 + rl + 8) * 96 + nc] =
                make_float2(acc[m][j][2] + bv.x + t1v.x, acc[m][j][3] + bv.y + t1v.y);
        }
    }
}

// ---------------------------------------------------------------------------
// patch merge (fp32 in/out), fp16 MMA engine, K chunks of 96
// ---------------------------------------------------------------------------
template <int DF, int KTOT, int WOUT>
__global__ __launch_bounds__(256, 3) void patch_tc(const float* __restrict__ x,
                                                   const float* __restrict__ w,
                                                   const float* __restrict__ bias,
                                                   float* __restrict__ out) {
    constexpr int KPAD = (KTOT + 15) & ~15;
    __shared__ uint4 As4[AS_U4];
    __shared__ uint4 Bs4[BS_U4];
    unsigned* As = (unsigned*)As4;
    unsigned* Bs = (unsigned*)Bs4;
    const int tid = threadIdx.x, lane = tid & 31, warp = tid >> 5;
    const int row0 = blockIdx.x * 128;
    const int T = WOUT * WOUT;
    const int mg = warp & 3, nh = warp >> 2;

    float acc[2][6][4];
#pragma unroll
    for (int m = 0; m < 2; ++m)
#pragma unroll
        for (int j = 0; j < 6; ++j)
#pragma unroll
            for (int i = 0; i < 4; ++i) acc[m][j][i] = 0.f;

    for (int kc = 0; kc < KPAD; kc += 96) {
        const int cl = (KPAD - kc) < 96 ? (KPAD - kc) : 96;
        const int nkt = cl >> 4;

        for (int idx = tid; idx < nkt * 768; idx += 256) {
            int kt = idx / 768;
            int r = idx - kt * 768;
            int jp = r >> 7;
            int r2 = r & 127;
            int ln = r2 >> 2, c = r2 & 3;
            int tig = ln & 3, gid = ln >> 2;
            int n = ((jp << 1) + (c >> 1)) * 8 + gid;
            int k = kc + kt * 16 + 2 * tig + ((c & 1) << 3);
            float lo = (k < KTOT) ? __ldg(&w[k * 96 + n]) : 0.f;
            float hi = (k + 1 < KTOT) ? __ldg(&w[(k + 1) * 96 + n]) : 0.f;
            Bs[idx] = f2h2(lo, hi);
        }
        {
            const int row = tid >> 1, sub = tid & 1;
            const int tok = row0 + row;
            const int b = tok / T, hw = tok - b * T;
            const int h = hw / WOUT, ww = hw - h * WOUT;
            const int mt = row >> 4, r16 = row & 15;
            const int gid8 = r16 & 7, rowhi = r16 >> 3;
#pragma unroll
            for (int j = 0; j < 12; ++j) {
                int k0 = sub * 48 + j * 4;
                if (k0 >= cl) break;
                float v[4];
#pragma unroll
                for (int e = 0; e < 4; ++e) {
                    int f = kc + k0 + e;
                    float vv = 0.f;
                    if (f < KTOT) {
                        int c2 = f / (DF * DF), rem = f - c2 * DF * DF;
                        int ki = rem / DF, kj = rem - ki * DF;
                        vv = __ldg(&x[((b * 3 + c2) * 224 + h * DF + ki) * 224 + ww * DF + kj]);
                    }
                    v[e] = vv;
                }
                int kt = k0 >> 4, kk = k0 & 15;
                int hi = kk >> 3, tig = (kk & 7) >> 1;
                unsigned base = (((kt * 8 + mt) * 32) + (gid8 << 2) + tig) * 4;
                As[base + (rowhi | (hi << 1))] = f2h2(v[0], v[1]);
                As[base + 4 + (rowhi | (hi << 1))] = f2h2(v[2], v[3]);
            }
        }
        __syncthreads();

        for (int kt = 0; kt < nkt; ++kt) {
            uint4 a0 = As4[(kt * 8 + mg * 2) * 32 + lane];
            uint4 a1 = As4[(kt * 8 + mg * 2 + 1) * 32 + lane];
            uint4 b0 = Bs4[(kt * 6 + nh * 3) * 32 + lane];
            uint4 b1 = Bs4[(kt * 6 + nh * 3 + 1) * 32 + lane];
            uint4 b2 = Bs4[(kt * 6 + nh * 3 + 2) * 32 + lane];
            mma16(acc[0][0], a0, b0.x, b0.y); mma16(acc[0][1], a0, b0.z, b0.w);
            mma16(acc[0][2], a0, b1.x, b1.y); mma16(acc[0][3], a0, b1.z, b1.w);
            mma16(acc[0][4], a0, b2.x, b2.y); mma16(acc[0][5], a0, b2.z, b2.w);
            mma16(acc[1][0], a1, b0.x, b0.y); mma16(acc[1][1], a1, b0.z, b0.w);
            mma16(acc[1][2], a1, b1.x, b1.y); mma16(acc[1][3], a1, b1.z, b1.w);
            mma16(acc[1][4], a1, b2.x, b2.y); mma16(acc[1][5], a1, b2.z, b2.w);
        }
        __syncthreads();
    }

    const int gid = lane >> 2, tig = lane & 3;
#pragma unroll
    for (int m = 0; m < 2; ++m) {
        int rr = row0 + (mg * 2 + m) * 16 + gid;
#pragma unroll
        for (int j = 0; j < 6; ++j) {
            int nc = (nh * 6 + j) * 8 + tig * 2;
            float2 bv = *(const float2*)&bias[nc];
            *(float2*)&out[(size_t)rr * 96 + nc] =
                make_float2(acc[m][j][0] + bv.x, acc[m][j][1] + bv.y);
            *(float2*)&out[(size_t)(rr + 8) * 96 + nc] =
                make_float2(acc[m][j][2] + bv.x, acc[m][j][3] + bv.y);
        }
    }
}

// ---------------------------------------------------------------------------
// window attention: fp16 in/out, fp32 math
// ---------------------------------------------------------------------------
template <int WS>
__global__ __launch_bounds__(128) void win_attn_k(const __half* __restrict__ qkv,
                                                  __half* __restrict__ o,
                                                  int Wout, int nw) {
    constexpr int NT = WS * WS;
    __shared__ float sq[NT][33], sk[NT][33], sv[NT][33];
    __shared__ float sS[NT * NT];
    const int b = blockIdx.x / (nw * nw);
    const int win = blockIdx.x % (nw * nw);
    const int wr = win / nw, wc = win % nw;
    const int t = threadIdx.x;
    const int T = Wout * Wout;
    const float scale = 0.17677669529663687f;

    for (int head = 0; head < 3; ++head) {
        for (int idx = t; idx < NT * 32; idx += 128) {
            int p = idx >> 5, c = idx & 31;
            int wi = p / WS, wj = p % WS;
            int r = b * T + (wr * WS + wi) * Wout + wc * WS + wj;
            const __half* base = qkv + (size_t)r * 288 + head * 32 + c;
            sq[p][c] = __half2float(base[0]);
            sk[p][c] = __half2float(base[96]);
            sv[p][c] = __half2float(base[192]);
        }
        __syncthreads();
        for (int idx = t; idx < NT * NT; idx += 128) {
            int i = idx / NT, j = idx % NT;
            float s = 0.f;
#pragma unroll
            for (int c = 0; c < 32; ++c) s = fmaf(sq[i][c], sk[j][c], s);
            sS[idx] = s * scale;
        }
        __syncthreads();
        if (t < NT) {
            float m = -1e30f;
            for (int j = 0; j < NT; ++j) m = fmaxf(m, sS[t * NT + j]);
            float Z = 0.f;
            for (int j = 0; j < NT; ++j) {
                float e = __expf(sS[t * NT + j] - m);
                sS[t * NT + j] = e;
                Z += e;
            }
            float inv = 1.f / Z;
            for (int j = 0; j < NT; ++j) sS[t * NT + j] *= inv;
        }
        __syncthreads();
        for (int idx = t; idx < NT * 32; idx += 128) {
            int i = idx >> 5, c = idx & 31;
            float acc = 0.f;
            for (int j = 0; j < NT; ++j) acc = fmaf(sS[i * NT + j], sv[j][c], acc);
            int wi = i / WS, wj = i % WS;
            int r = b * T + (wr * WS + wi) * Wout + wc * WS + wj;
            o[(size_t)r * 96 + head * 32 + c] = __float2half(acc);
        }
        __syncthreads();
    }
}

// ---------------------------------------------------------------------------
// neighbor gather + LN (scrambled unfold reshape), fp32 in, fp16 out
// ---------------------------------------------------------------------------
__global__ __launch_bounds__(96) void gather_ln_k(const float* __restrict__ t1,
                                                  const float* __restrict__ t2,
                                                  const float* __restrict__ g,
                                                  const float* __restrict__ bb,
                                                  __half* __restrict__ kv) {
    const int b = blockIdx.x / 196, l = blockIdx.x % 196;
    const int i1 = l / 14, j1 = l % 14;
    __shared__ float s1[16 * 97];
    __shared__ float s2[9 * 97];
    __shared__ float red[2][3];
    const int t = threadIdx.x, warp = t >> 5, lane = t & 31;

    for (int p = 0; p < 16; ++p) {
        int ki = p >> 2, kj = p & 3;
        s1[p * 97 + t] = t1[(size_t)((b * 56 + i1 * 4 + ki) * 56 + j1 * 4 + kj) * 96 + t];
    }
    for (int p = 0; p < 9; ++p) {
        int ki = p / 3, kj = p % 3;
        int rr = i1 * 3 + ki - 5, cc = j1 * 3 + kj - 5;
        float v = 0.f;
        if (rr >= 0 && rr < 32 && cc >= 0 && cc < 32)
            v = t2[(size_t)((b * 32 + rr) * 32 + cc) * 96 + t];
        s2[p * 97 + t] = v;
    }
    __syncthreads();
    const float gg = g[t], bv = bb[t];

    for (int k = 0; k < 25; ++k) {
        float v;
        if (k < 16) {
            int F = k * 96 + t;
            int c = F >> 4, rem = F & 15;
            v = s1[rem * 97 + c];
        } else {
            int F = (k - 16) * 96 + t;
            int c = F / 9, rem = F % 9;
            v = s2[rem * 97 + c];
        }
        float s = v, s2s = v * v;
#pragma unroll
        for (int o = 16; o > 0; o >>= 1) {
            s += __shfl_xor_sync(0xffffffffu, s, o);
            s2s += __shfl_xor_sync(0xffffffffu, s2s, o);
        }
        if (lane == 0) { red[0][warp] = s; red[1][warp] = s2s; }
        __syncthreads();
        float S = red[0][0] + red[0][1] + red[0][2];
        float S2 = red[1][0] + red[1][1] + red[1][2];
        float mean = S * (1.f / 96.f);
        float var = fmaf(-mean, mean, S2 * (1.f / 96.f));
        kv[((size_t)blockIdx.x * 25 + k) * 96 + t] =
            __float2half((v - mean) * rsqrtf(var + 1e-5f) * gg + bv);
        __syncthreads();
    }
}

// ---------------------------------------------------------------------------
// cross attention: fp16 in/out, fp32 math
// ---------------------------------------------------------------------------
__global__ __launch_bounds__(96) void cross_attn_k(const __half* __restrict__ q,
                                                   const __half* __restrict__ kbuf,
                                                   const __half* __restrict__ vbuf,
                                                   __half* __restrict__ o) {
    const int rl = blockIdx.x;
    __shared__ float sk[25][97], sv[25][97], sq[96], ss[25];
    const int t = threadIdx.x;
    sq[t] = __half2float(q[(size_t)rl * 96 + t]);
    for (int k = 0; k < 25; ++k) {
        sk[k][t] = __half2float(kbuf[((size_t)rl * 25 + k) * 96 + t]);
        sv[k][t] = __half2float(vbuf[((size_t)rl * 25 + k) * 96 + t]);
    }
    __syncthreads();
    if (t < 25) {
        float s = 0.f;
        for (int c = 0; c < 96; ++c) s = fmaf(sq[c], sk[t][c], s);
        ss[t] = s * 0.10206207261596575f;
    }
    __syncthreads();
    float m = -1e30f;
#pragma unroll
    for (int k = 0; k < 25; ++k) m = fmaxf(m, ss[k]);
    float Z = 0.f, acc = 0.f;
#pragma unroll
    for (int k = 0; k < 25; ++k) {
        float e = __expf(ss[k] - m);
        Z += e;
        acc = fmaf(e, sv[k][t], acc);
    }
    o[(size_t)rl * 96 + t] = __float2half(acc / Z);
}

// ---------------------------------------------------------------------------
extern "C" void kernel_launch(void* const* d_in, const int* in_sizes, int n_in,
                              void* d_out, int out_size) {
    const float* x       = (const float*)d_in[0];
    const float* pw[3]   = {(const float*)d_in[1], (const float*)d_in[3], (const float*)d_in[5]};
    const float* pb[3]   = {(const float*)d_in[2], (const float*)d_in[4], (const float*)d_in[6]};
    const float* wa_ln_g = (const float*)d_in[7];
    const float* wa_ln_b = (const float*)d_in[8];
    const float* wa_qkv  = (const float*)d_in[9];
    const float* wa_ow   = (const float*)d_in[10];
    const float* wa_ob   = (const float*)d_in[11];
    const float* ff_ln_g = (const float*)d_in[12];
    const float* ff_ln_b = (const float*)d_in[13];
    const float* ff_w1   = (const float*)d_in[14];
    const float* ff_b1   = (const float*)d_in[15];
    const float* ff_w2   = (const float*)d_in[16];
    const float* ff_b2   = (const float*)d_in[17];
    const float* lnn_g   = (const float*)d_in[18];
    const float* lnn_b   = (const float*)d_in[19];
    const float* ca_wq   = (const float*)d_in[20];
    const float* ca_wk   = (const float*)d_in[21];
    const float* ca_wv   = (const float*)d_in[22];
    const float* ca_wo   = (const float*)d_in[23];
    const float* ca_bo   = (const float*)d_in[24];
    const float* fi_ln_g = (const float*)d_in[25];
    const float* fi_ln_b = (const float*)d_in[26];
    const float* fi_w1   = (const float*)d_in[27];
    const float* fi_b1   = (const float*)d_in[28];
    const float* fi_w2   = (const float*)d_in[29];
    const float* fi_b2   = (const float*)d_in[30];
    float* out = (float*)d_out;

    float *t0, *t1, *t2;
    __half *qkv, *ob, *kv, *kk, *vv, *qq, *co;
    cudaGetSymbolAddress((void**)&t0, g_t0);
    cudaGetSymbolAddress((void**)&t1, g_t1);
    cudaGetSymbolAddress((void**)&t2, g_t2);
    cudaGetSymbolAddress((void**)&qkv, g_qkv);
    cudaGetSymbolAddress((void**)&ob, g_ob);
    cudaGetSymbolAddress((void**)&kv, g_kv);
    cudaGetSymbolAddress((void**)&kk, g_k);
    cudaGetSymbolAddress((void**)&vv, g_v);
    cudaGetSymbolAddress((void**)&qq, g_q);
    cudaGetSymbolAddress((void**)&co, g_co);

    cudaFuncSetAttribute(resff_tc, cudaFuncAttributeMaxDynamicSharedMemorySize, RES_SMEM);

    // patch merges
    patch_tc<16, 768, 14><<<ROWS0 / 128, 256>>>(x, pw[0], pb[0], t0);
    patch_tc<4, 48, 56><<<ROWS1 / 128, 256>>>(x, pw[1], pb[1], t1);
    patch_tc<7, 147, 32><<<ROWS2 / 128, 256>>>(x, pw[2], pb[2], t2);

    const int rows[3] = {ROWS0, ROWS1, ROWS2};
    float* tb[3] = {t0, t1, t2};
    for (int i = 0; i < 3; ++i) {
        const int R = rows[i];
        float* t = tb[i];
        // qkv(fp16) = LN(t) @ Wqkv
        gemm_tc<float, __half, true, false, 0, false><<<dim3(R / 128, 3), 256>>>(
            t, wa_qkv + i * 96 * 288, nullptr, nullptr,
            wa_ln_g + i * 96, wa_ln_b + i * 96, nullptr, qkv, nullptr, 288);
        if (i == 0)      win_attn_k<7><<<64 * 2 * 2, 128>>>(qkv, ob, 14, 2);
        else if (i == 1) win_attn_k<4><<<64 * 14 * 14, 128>>>(qkv, ob, 56, 14);
        else             win_attn_k<4><<<64 * 8 * 8, 128>>>(qkv, ob, 32, 8);
        // fused: t = (t + ob@Wo + bo); t += gelu(LN(t)@W1+b1)@W2 + b2
        resff_tc<<<R / 128, 256, RES_SMEM>>>(
            ob, t, t, wa_ow + i * 9216, wa_ob + i * 96,
            ff_ln_g + i * 96, ff_ln_b + i * 96,
            ff_w1 + i * 9216, ff_b1 + i * 96, ff_w2 + i * 9216, ff_b2 + i * 96);
    }

    // neighbor gather + LN -> kv(fp16)
    gather_ln_k<<<64 * 196, 96>>>(t1, t2, lnn_g, lnn_b, kv);
    // k/v projections in one dual launch
    gemm_tc<__half, __half, false, false, 0, true><<<dim3(KVROWS / 128, 2), 256>>>(
        kv, ca_wk, ca_wv, nullptr, nullptr, nullptr, nullptr, kk, vv, 96);
    // q(fp16) = LN(t0) @ Wq
    gemm_tc<float, __half, true, false, 0, false><<<dim3(ROWS0 / 128, 1), 256>>>(
        t0, ca_wq, nullptr, nullptr, lnn_g, lnn_b, nullptr, qq, nullptr, 96);
    // cross attention
    cross_attn_k<<<12544, 96>>>(qq, kk, vv, co);
    // fused final: out = (t0 + co@Wo + bo); out += gelu(LN(out)@w1+b1)@w2 + b2
    resff_tc<<<ROWS0 / 128, 256, RES_SMEM>>>(
        co, t0, out, ca_wo, ca_bo, fi_ln_g, fi_ln_b,
        fi_w1, fi_b1, fi_w2, fi_b2);
}

// round 8
// speedup vs baseline: 1.0051x; 1.0051x over previous
#include <cuda_runtime.h>
#include <cuda_fp16.h>
#include <math.h>

// ---------------------------------------------------------------------------
// MultiScaleCrossAttn — fp16 MMA GEMMs (R5 engine) + vectorized scalar kernels
// ---------------------------------------------------------------------------

#define ROWS0 12544      // 64*14*14
#define ROWS1 200704     // 64*56*56
#define ROWS2 65536      // 64*32*32
#define KVROWS 313600    // 64*196*25

__device__ float g_t0[ROWS0 * 96];
__device__ float g_t1[ROWS1 * 96];
__device__ float g_t2[ROWS2 * 96];
__device__ __align__(16) __half g_qkv[ROWS1 * 288];
__device__ __align__(16) __half g_ob[ROWS1 * 96];
__device__ __align__(16) __half g_kv[KVROWS * 96];
__device__ __align__(16) __half g_k[KVROWS * 96];
__device__ __align__(16) __half g_v[KVROWS * 96];
__device__ __align__(16) __half g_q[ROWS0 * 96];
__device__ __align__(16) __half g_co[ROWS0 * 96];

static constexpr int AS_U4 = 6 * 8 * 32;   // 24KB
static constexpr int BS_U4 = 6 * 6 * 32;   // 18KB

__device__ __forceinline__ unsigned f2h2(float lo, float hi) {
    __half2 h = __floats2half2_rn(lo, hi);
    return *reinterpret_cast<unsigned*>(&h);
}

__device__ __forceinline__ void mma16(float c[4], uint4 a, unsigned b0, unsigned b1) {
    asm volatile(
        "mma.sync.aligned.m16n8k16.row.col.f32.f16.f16.f32 "
        "{%0,%1,%2,%3}, {%4,%5,%6,%7}, {%8,%9}, {%0,%1,%2,%3};\n"
        : "+f"(c[0]), "+f"(c[1]), "+f"(c[2]), "+f"(c[3])
        : "r"(a.x), "r"(a.y), "r"(a.z), "r"(a.w), "r"(b0), "r"(b1));
}

__device__ __forceinline__ float gelu_f(float v) {
    return 0.5f * v * (1.f + erff(v * 0.70710678118654752f));
}

__device__ __forceinline__ void gemm_main(float acc[2][6][4], const uint4* As4,
                                          const uint4* Bs4, int mg, int nh, int lane) {
#pragma unroll
    for (int m = 0; m < 2; ++m)
#pragma unroll
        for (int j = 0; j < 6; ++j)
#pragma unroll
            for (int i = 0; i < 4; ++i) acc[m][j][i] = 0.f;
#pragma unroll
    for (int kt = 0; kt < 6; ++kt) {
        uint4 a0 = As4[(kt * 8 + mg * 2) * 32 + lane];
        uint4 a1 = As4[(kt * 8 + mg * 2 + 1) * 32 + lane];
        uint4 b0 = Bs4[(kt * 6 + nh * 3) * 32 + lane];
        uint4 b1 = Bs4[(kt * 6 + nh * 3 + 1) * 32 + lane];
        uint4 b2 = Bs4[(kt * 6 + nh * 3 + 2) * 32 + lane];
        mma16(acc[0][0], a0, b0.x, b0.y); mma16(acc[0][1], a0, b0.z, b0.w);
        mma16(acc[0][2], a0, b1.x, b1.y); mma16(acc[0][3], a0, b1.z, b1.w);
        mma16(acc[0][4], a0, b2.x, b2.y); mma16(acc[0][5], a0, b2.z, b2.w);
        mma16(acc[1][0], a1, b0.x, b0.y); mma16(acc[1][1], a1, b0.z, b0.w);
        mma16(acc[1][2], a1, b1.x, b1.y); mma16(acc[1][3], a1, b1.z, b1.w);
        mma16(acc[1][4], a1, b2.x, b2.y); mma16(acc[1][5], a1, b2.z, b2.w);
    }
}

__device__ __forceinline__ void stage_B(unsigned* Bs, const float* W, int ldw,
                                        int ncol0, int tid) {
    for (int idx = tid; idx < BS_U4 * 4; idx += 256) {
        int kt = idx / 768;
        int r = idx - kt * 768;
        int jp = r >> 7;
        int r2 = r & 127;
        int ln = r2 >> 2, c = r2 & 3;
        int tig = ln & 3, gid = ln >> 2;
        int n = ncol0 + ((jp << 1) + (c >> 1)) * 8 + gid;
        int k = kt * 16 + 2 * tig + ((c & 1) << 3);
        Bs[idx] = f2h2(__ldg(&W[k * ldw + n]), __ldg(&W[(k + 1) * ldw + n]));
    }
}

// ---------------------------------------------------------------------------
// generic GEMM: TA/TO in {float,__half}; optional LN (fp32 input), GELU;
// EPI 0 store / 1 += / 2 res+; DUAL: blockIdx.y picks (W,out) vs (W2,out2)
// ---------------------------------------------------------------------------
template <class TA, class TO, bool LNF, bool GELU, int EPI, bool DUAL>
__global__ __launch_bounds__(256, 3) void gemm_tc(const TA* __restrict__ A,
                                                  const float* __restrict__ W,
                                                  const float* __restrict__ W2,
                                                  const float* __restrict__ bias,
                                                  const float* __restrict__ lng,
                                                  const float* __restrict__ lnb,
                                                  const float* __restrict__ res,
                                                  TO* __restrict__ out,
                                                  TO* __restrict__ out2, int ldw) {
    constexpr bool TAH = (sizeof(TA) == 2);
    constexpr bool TOH = (sizeof(TO) == 2);
    __shared__ uint4 As4[AS_U4];
    __shared__ uint4 Bs4[BS_U4];
    unsigned* As = (unsigned*)As4;
    unsigned* Bs = (unsigned*)Bs4;
    const int tid = threadIdx.x, lane = tid & 31, warp = tid >> 5;
    const int row0 = blockIdx.x * 128;
    int ncol0 = 0;
    if (DUAL) {
        if (blockIdx.y) { W = W2; out = out2; }
    } else {
        ncol0 = blockIdx.y * 96;
    }

    stage_B(Bs, W, ldw, ncol0, tid);

    {
        const int row = tid >> 1, sub = tid & 1;
        const int mt = row >> 4, r16 = row & 15;
        const int gid8 = r16 & 7, rowhi = r16 >> 3;
        if constexpr (TAH) {
            const uint4* ap = (const uint4*)((const __half*)A + (size_t)(row0 + row) * 96 + sub * 48);
#pragma unroll
            for (int j = 0; j < 6; ++j) {
                uint4 u = __ldg(&ap[j]);
                unsigned w[4] = {u.x, u.y, u.z, u.w};
#pragma unroll
                for (int wi = 0; wi < 4; ++wi) {
                    int P = sub * 24 + j * 4 + wi;
                    int kt = P >> 3, hi = (P >> 2) & 1, tg = P & 3;
                    As[(((kt * 8 + mt) * 32) + (gid8 << 2) + tg) * 4 + (rowhi | (hi << 1))] = w[wi];
                }
            }
        } else {
            const float* ap = (const float*)A + (size_t)(row0 + row) * 96 + sub * 48;
            float4 vals[12];
#pragma unroll
            for (int j = 0; j < 12; ++j) vals[j] = __ldg((const float4*)(ap + j * 4));
            float mean = 0.f, rstd = 0.f;
            if (LNF) {
                float s = 0.f, s2 = 0.f;
#pragma unroll
                for (int j = 0; j < 12; ++j) {
                    float4 v = vals[j];
                    s += v.x + v.y + v.z + v.w;
                    s2 += v.x * v.x + v.y * v.y + v.z * v.z + v.w * v.w;
                }
                s += __shfl_xor_sync(0xffffffffu, s, 1);
                s2 += __shfl_xor_sync(0xffffffffu, s2, 1);
                mean = s * (1.f / 96.f);
                float var = fmaf(-mean, mean, s2 * (1.f / 96.f));
                rstd = rsqrtf(var + 1e-5f);
            }
#pragma unroll
            for (int j = 0; j < 12; ++j) {
                int k0 = sub * 48 + j * 4;
                float4 v = vals[j];
                if (LNF) {
                    float4 g = __ldg((const float4*)(lng + k0));
                    float4 bb = __ldg((const float4*)(lnb + k0));
                    v.x = (v.x - mean) * rstd * g.x + bb.x;
                    v.y = (v.y - mean) * rstd * g.y + bb.y;
                    v.z = (v.z - mean) * rstd * g.z + bb.z;
                    v.w = (v.w - mean) * rstd * g.w + bb.w;
                }
                int kt = k0 >> 4, kk = k0 & 15;
                int hi = kk >> 3, tig = (kk & 7) >> 1;
                unsigned base = (((kt * 8 + mt) * 32) + (gid8 << 2) + tig) * 4;
                As[base + (rowhi | (hi << 1))] = f2h2(v.x, v.y);
                As[base + 4 + (rowhi | (hi << 1))] = f2h2(v.z, v.w);
            }
        }
    }
    __syncthreads();

    const int mg = warp & 3, nh = warp >> 2;
    float acc[2][6][4];
    gemm_main(acc, As4, Bs4, mg, nh, lane);

    const int gid = lane >> 2, tig = lane & 3;
#pragma unroll
    for (int m = 0; m < 2; ++m) {
        int rr = row0 + (mg * 2 + m) * 16 + gid;
#pragma unroll
        for (int j = 0; j < 6; ++j) {
            int nc = ncol0 + (nh * 6 + j) * 8 + tig * 2;
            float bx = 0.f, by = 0.f;
            if (bias) {
                float2 bv = *(const float2*)&bias[nc];
                bx = bv.x; by = bv.y;
            }
            float x0 = acc[m][j][0] + bx, x1 = acc[m][j][1] + by;
            float x2 = acc[m][j][2] + bx, x3 = acc[m][j][3] + by;
            if (GELU) { x0 = gelu_f(x0); x1 = gelu_f(x1); x2 = gelu_f(x2); x3 = gelu_f(x3); }
            if constexpr (TOH) {
                __half2* p0 = (__half2*)((__half*)out + (size_t)rr * ldw + nc);
                __half2* p1 = (__half2*)((__half*)out + (size_t)(rr + 8) * ldw + nc);
                *p0 = __floats2half2_rn(x0, x1);
                *p1 = __floats2half2_rn(x2, x3);
            } else {
                float* p0 = (float*)out + (size_t)rr * ldw + nc;
                float* p1 = (float*)out + (size_t)(rr + 8) * ldw + nc;
                if constexpr (EPI == 0) {
                    *(float2*)p0 = make_float2(x0, x1);
                    *(float2*)p1 = make_float2(x2, x3);
                } else if constexpr (EPI == 1) {
                    float2 o0 = *(float2*)p0, o1 = *(float2*)p1;
                    *(float2*)p0 = make_float2(o0.x + x0, o0.y + x1);
                    *(float2*)p1 = make_float2(o1.x + x2, o1.y + x3);
                } else {
                    float2 r0 = *(const float2*)&res[(size_t)rr * 96 + nc];
                    float2 r1 = *(const float2*)&res[(size_t)(rr + 8) * 96 + nc];
                    *(float2*)p0 = make_float2(r0.x + x0, r0.y + x1);
                    *(float2*)p1 = make_float2(r1.x + x2, r1.y + x3);
                }
            }
        }
    }
}

// ---------------------------------------------------------------------------
// patch merge (fp32 in/out), fp16 MMA engine, K chunks of 96
// ---------------------------------------------------------------------------
template <int DF, int KTOT, int WOUT>
__global__ __launch_bounds__(256, 3) void patch_tc(const float* __restrict__ x,
                                                   const float* __restrict__ w,
                                                   const float* __restrict__ bias,
                                                   float* __restrict__ out) {
    constexpr int KPAD = (KTOT + 15) & ~15;
    __shared__ uint4 As4[AS_U4];
    __shared__ uint4 Bs4[BS_U4];
    unsigned* As = (unsigned*)As4;
    unsigned* Bs = (unsigned*)Bs4;
    const int tid = threadIdx.x, lane = tid & 31, warp = tid >> 5;
    const int row0 = blockIdx.x * 128;
    const int T = WOUT * WOUT;
    const int mg = warp & 3, nh = warp >> 2;

    float acc[2][6][4];
#pragma unroll
    for (int m = 0; m < 2; ++m)
#pragma unroll
        for (int j = 0; j < 6; ++j)
#pragma unroll
            for (int i = 0; i < 4; ++i) acc[m][j][i] = 0.f;

    for (int kc = 0; kc < KPAD; kc += 96) {
        const int cl = (KPAD - kc) < 96 ? (KPAD - kc) : 96;
        const int nkt = cl >> 4;

        for (int idx = tid; idx < nkt * 768; idx += 256) {
            int kt = idx / 768;
            int r = idx - kt * 768;
            int jp = r >> 7;
            int r2 = r & 127;
            int ln = r2 >> 2, c = r2 & 3;
            int tig = ln & 3, gid = ln >> 2;
            int n = ((jp << 1) + (c >> 1)) * 8 + gid;
            int k = kc + kt * 16 + 2 * tig + ((c & 1) << 3);
            float lo = (k < KTOT) ? __ldg(&w[k * 96 + n]) : 0.f;
            float hi = (k + 1 < KTOT) ? __ldg(&w[(k + 1) * 96 + n]) : 0.f;
            Bs[idx] = f2h2(lo, hi);
        }
        {
            const int row = tid >> 1, sub = tid & 1;
            const int tok = row0 + row;
            const int b = tok / T, hw = tok - b * T;
            const int h = hw / WOUT, ww = hw - h * WOUT;
            const int mt = row >> 4, r16 = row & 15;
            const int gid8 = r16 & 7, rowhi = r16 >> 3;
#pragma unroll
            for (int j = 0; j < 12; ++j) {
                int k0 = sub * 48 + j * 4;
                if (k0 >= cl) break;
                float v[4];
#pragma unroll
                for (int e = 0; e < 4; ++e) {
                    int f = kc + k0 + e;
                    float vv = 0.f;
                    if (f < KTOT) {
                        int c2 = f / (DF * DF), rem = f - c2 * DF * DF;
                        int ki = rem / DF, kj = rem - ki * DF;
                        vv = __ldg(&x[((b * 3 + c2) * 224 + h * DF + ki) * 224 + ww * DF + kj]);
                    }
                    v[e] = vv;
                }
                int kt = k0 >> 4, kk = k0 & 15;
                int hi = kk >> 3, tig = (kk & 7) >> 1;
                unsigned base = (((kt * 8 + mt) * 32) + (gid8 << 2) + tig) * 4;
                As[base + (rowhi | (hi << 1))] = f2h2(v[0], v[1]);
                As[base + 4 + (rowhi | (hi << 1))] = f2h2(v[2], v[3]);
            }
        }
        __syncthreads();

        for (int kt = 0; kt < nkt; ++kt) {
            uint4 a0 = As4[(kt * 8 + mg * 2) * 32 + lane];
            uint4 a1 = As4[(kt * 8 + mg * 2 + 1) * 32 + lane];
            uint4 b0 = Bs4[(kt * 6 + nh * 3) * 32 + lane];
            uint4 b1 = Bs4[(kt * 6 + nh * 3 + 1) * 32 + lane];
            uint4 b2 = Bs4[(kt * 6 + nh * 3 + 2) * 32 + lane];
            mma16(acc[0][0], a0, b0.x, b0.y); mma16(acc[0][1], a0, b0.z, b0.w);
            mma16(acc[0][2], a0, b1.x, b1.y); mma16(acc[0][3], a0, b1.z, b1.w);
            mma16(acc[0][4], a0, b2.x, b2.y); mma16(acc[0][5], a0, b2.z, b2.w);
            mma16(acc[1][0], a1, b0.x, b0.y); mma16(acc[1][1], a1, b0.z, b0.w);
            mma16(acc[1][2], a1, b1.x, b1.y); mma16(acc[1][3], a1, b1.z, b1.w);
            mma16(acc[1][4], a1, b2.x, b2.y); mma16(acc[1][5], a1, b2.z, b2.w);
        }
        __syncthreads();
    }

    const int gid = lane >> 2, tig = lane & 3;
#pragma unroll
    for (int m = 0; m < 2; ++m) {
        int rr = row0 + (mg * 2 + m) * 16 + gid;
#pragma unroll
        for (int j = 0; j < 6; ++j) {
            int nc = (nh * 6 + j) * 8 + tig * 2;
            float2 bv = *(const float2*)&bias[nc];
            *(float2*)&out[(size_t)rr * 96 + nc] =
                make_float2(acc[m][j][0] + bv.x, acc[m][j][1] + bv.y);
            *(float2*)&out[(size_t)(rr + 8) * 96 + nc] =
                make_float2(acc[m][j][2] + bv.x, acc[m][j][3] + bv.y);
        }
    }
}

// ---------------------------------------------------------------------------
// window attention: ALL 3 heads in parallel, vectorized uint4 loads.
// dyn smem: sq/sk/sv [3][NT][33] floats + sS [3][NT][NT]
// ---------------------------------------------------------------------------
template <int WS>
__global__ __launch_bounds__(128) void win_attn_k(const __half* __restrict__ qkv,
                                                  __half* __restrict__ o,
                                                  int Wout, int nw) {
    constexpr int NT = WS * WS;
    extern __shared__ float wsm[];
    float* sq = wsm;                    // [3][NT][33]
    float* sk = sq + 3 * NT * 33;
    float* sv = sk + 3 * NT * 33;
    float* sS = sv + 3 * NT * 33;       // [3][NT][NT]
    const int b = blockIdx.x / (nw * nw);
    const int win = blockIdx.x % (nw * nw);
    const int wr = win / nw, wc = win % nw;
    const int t = threadIdx.x;
    const int T = Wout * Wout;
    const float scale = 0.17677669529663687f;  // 1/sqrt(32)

    // load: each window row = 288 halves = 36 uint4
    for (int idx = t; idx < NT * 36; idx += 128) {
        int p = idx / 36, u = idx - p * 36;
        int wi = p / WS, wj = p - wi * WS;
        int r = b * T + (wr * WS + wi) * Wout + wc * WS + wj;
        uint4 val = __ldg((const uint4*)(qkv + (size_t)r * 288) + u);
        int sec = u / 12, uu = u - sec * 12;
        int head = uu >> 2, c0 = (uu & 3) * 8;
        float* dst = (sec == 0 ? sq : sec == 1 ? sk : sv) + (head * NT + p) * 33 + c0;
        __half2* h2 = (__half2*)&val;
#pragma unroll
        for (int e = 0; e < 4; ++e) {
            float2 f = __half22float2(h2[e]);
            dst[2 * e] = f.x;
            dst[2 * e + 1] = f.y;
        }
    }
    __syncthreads();

    // QK^T for all heads
    for (int idx = t; idx < 3 * NT * NT; idx += 128) {
        int h = idx / (NT * NT);
        int ij = idx - h * NT * NT;
        int i = ij / NT, j = ij - i * NT;
        const float* qi = sq + (h * NT + i) * 33;
        const float* kj = sk + (h * NT + j) * 33;
        float s = 0.f;
#pragma unroll
        for (int c = 0; c < 32; ++c) s = fmaf(qi[c], kj[c], s);
        sS[idx] = s * scale;
    }
    __syncthreads();

    // softmax rows (3*NT rows)
    for (int row = t; row < 3 * NT; row += 128) {
        float* p = sS + row * NT;
        float m = -1e30f;
        for (int j = 0; j < NT; ++j) m = fmaxf(m, p[j]);
        float Z = 0.f;
        for (int j = 0; j < NT; ++j) {
            float e = __expf(p[j] - m);
            p[j] = e;
            Z += e;
        }
        float inv = 1.f / Z;
        for (int j = 0; j < NT; ++j) p[j] *= inv;
    }
    __syncthreads();

    // AV
    for (int idx = t; idx < 3 * NT * 32; idx += 128) {
        int h = idx / (NT * 32);
        int rest = idx - h * NT * 32;
        int i = rest >> 5, c = rest & 31;
        const float* pw = sS + (h * NT + i) * NT;
        const float* vb = sv + h * NT * 33 + c;
        float acc = 0.f;
        for (int j = 0; j < NT; ++j) acc = fmaf(pw[j], vb[j * 33], acc);
        int wi = i / WS, wj = i - wi * WS;
        int r = b * T + (wr * WS + wi) * Wout + wc * WS + wj;
        o[(size_t)r * 96 + h * 32 + c] = __float2half(acc);
    }
}

// ---------------------------------------------------------------------------
// neighbor gather + LN: 256 thr, warp-per-row LN, no block syncs after load
// ---------------------------------------------------------------------------
__global__ __launch_bounds__(256) void gather_ln_k(const float* __restrict__ t1,
                                                   const float* __restrict__ t2,
                                                   const float* __restrict__ g,
                                                   const float* __restrict__ bb,
                                                   __half* __restrict__ kv) {
    const int bl = blockIdx.x;
    const int b = bl / 196, l = bl % 196;
    const int i1 = l / 14, j1 = l % 14;
    __shared__ float s1[16 * 100];
    __shared__ float s2[9 * 100];
    const int tid = threadIdx.x, warp = tid >> 5, lane = tid & 31;

    // stage: 16 rows (scale1 4x4 patch), 24 float4 each
    for (int idx = tid; idx < 16 * 24; idx += 256) {
        int p = idx / 24, q = idx - p * 24;
        int ki = p >> 2, kj = p & 3;
        const float4 v = __ldg((const float4*)(t1 +
            (size_t)((b * 56 + i1 * 4 + ki) * 56 + j1 * 4 + kj) * 96 + q * 4));
        *(float4*)&s1[p * 100 + q * 4] = v;
    }
    // stage: 9 rows (scale2 3x3 padded patch)
    for (int idx = tid; idx < 9 * 24; idx += 256) {
        int p = idx / 24, q = idx - p * 24;
        int ki = p / 3, kj = p - ki * 3;
        int rr = i1 * 3 + ki - 5, cc = j1 * 3 + kj - 5;
        float4 v = make_float4(0.f, 0.f, 0.f, 0.f);
        if (rr >= 0 && rr < 32 && cc >= 0 && cc < 32)
            v = __ldg((const float4*)(t2 + (size_t)((b * 32 + rr) * 32 + cc) * 96 + q * 4));
        *(float4*)&s2[p * 100 + q * 4] = v;
    }
    __syncthreads();

    float gv[3], bv[3];
#pragma unroll
    for (int i = 0; i < 3; ++i) {
        gv[i] = __ldg(&g[lane + 32 * i]);
        bv[i] = __ldg(&bb[lane + 32 * i]);
    }

    for (int k = warp; k < 25; k += 8) {
        float v[3];
#pragma unroll
        for (int i = 0; i < 3; ++i) {
            int c = lane + 32 * i;
            if (k < 16) {
                int F = k * 96 + c;
                v[i] = s1[(F & 15) * 100 + (F >> 4)];
            } else {
                int F = (k - 16) * 96 + c;
                v[i] = s2[(F % 9) * 100 + (F / 9)];
            }
        }
        float s = v[0] + v[1] + v[2];
        float q = v[0] * v[0] + v[1] * v[1] + v[2] * v[2];
#pragma unroll
        for (int off = 16; off > 0; off >>= 1) {
            s += __shfl_xor_sync(0xffffffffu, s, off);
            q += __shfl_xor_sync(0xffffffffu, q, off);
        }
        float mean = s * (1.f / 96.f);
        float var = fmaf(-mean, mean, q * (1.f / 96.f));
        float rstd = rsqrtf(var + 1e-5f);
        __half* dst = kv + ((size_t)bl * 25 + k) * 96;
#pragma unroll
        for (int i = 0; i < 3; ++i)
            dst[lane + 32 * i] = __float2half((v[i] - mean) * rstd * gv[i] + bv[i]);
    }
}

// ---------------------------------------------------------------------------
// cross attention: contiguous 25x96 K/V block staged via uint4, 128 thr
// ---------------------------------------------------------------------------
__global__ __launch_bounds__(128) void cross_attn_k(const __half* __restrict__ q,
                                                    const __half* __restrict__ kbuf,
                                                    const __half* __restrict__ vbuf,
                                                    __half* __restrict__ o) {
    const int rl = blockIdx.x;
    __shared__ __half hk[2400], hv[2400];
    __shared__ float sqf[96], ss[25];
    const int t = threadIdx.x;

    const uint4* ksrc = (const uint4*)(kbuf + (size_t)rl * 2400);
    const uint4* vsrc = (const uint4*)(vbuf + (size_t)rl * 2400);
    for (int idx = t; idx < 300; idx += 128) {
        ((uint4*)hk)[idx] = __ldg(ksrc + idx);
        ((uint4*)hv)[idx] = __ldg(vsrc + idx);
    }
    if (t < 96) sqf[t] = __half2float(__ldg(q + (size_t)rl * 96 + t));
    __syncthreads();

    if (t < 25) {
        const __half* kr = hk + t * 96;
        float s = 0.f;
#pragma unroll 8
        for (int c = 0; c < 96; ++c) s = fmaf(sqf[c], __half2float(kr[c]), s);
        ss[t] = s * 0.10206207261596575f;  // 1/sqrt(96)
    }
    __syncthreads();

    if (t < 96) {
        float m = -1e30f;
#pragma unroll
        for (int k = 0; k < 25; ++k) m = fmaxf(m, ss[k]);
        float Z = 0.f, acc = 0.f;
#pragma unroll
        for (int k = 0; k < 25; ++k) {
            float e = __expf(ss[k] - m);
            Z += e;
            acc = fmaf(e, __half2float(hv[k * 96 + t]), acc);
        }
        o[(size_t)rl * 96 + t] = __float2half(acc / Z);
    }
}

// ---------------------------------------------------------------------------
extern "C" void kernel_launch(void* const* d_in, const int* in_sizes, int n_in,
                              void* d_out, int out_size) {
    const float* x       = (const float*)d_in[0];
    const float* pw[3]   = {(const float*)d_in[1], (const float*)d_in[3], (const float*)d_in[5]};
    const float* pb[3]   = {(const float*)d_in[2], (const float*)d_in[4], (const float*)d_in[6]};
    const float* wa_ln_g = (const float*)d_in[7];
    const float* wa_ln_b = (const float*)d_in[8];
    const float* wa_qkv  = (const float*)d_in[9];
    const float* wa_ow   = (const float*)d_in[10];
    const float* wa_ob   = (const float*)d_in[11];
    const float* ff_ln_g = (const float*)d_in[12];
    const float* ff_ln_b = (const float*)d_in[13];
    const float* ff_w1   = (const float*)d_in[14];
    const float* ff_b1   = (const float*)d_in[15];
    const float* ff_w2   = (const float*)d_in[16];
    const float* ff_b2   = (const float*)d_in[17];
    const float* lnn_g   = (const float*)d_in[18];
    const float* lnn_b   = (const float*)d_in[19];
    const float* ca_wq   = (const float*)d_in[20];
    const float* ca_wk   = (const float*)d_in[21];
    const float* ca_wv   = (const float*)d_in[22];
    const float* ca_wo   = (const float*)d_in[23];
    const float* ca_bo   = (const float*)d_in[24];
    const float* fi_ln_g = (const float*)d_in[25];
    const float* fi_ln_b = (const float*)d_in[26];
    const float* fi_w1   = (const float*)d_in[27];
    const float* fi_b1   = (const float*)d_in[28];
    const float* fi_w2   = (const float*)d_in[29];
    const float* fi_b2   = (const float*)d_in[30];
    float* out = (float*)d_out;

    float *t0, *t1, *t2;
    __half *qkv, *ob, *kv, *kk, *vv, *qq, *co;
    cudaGetSymbolAddress((void**)&t0, g_t0);
    cudaGetSymbolAddress((void**)&t1, g_t1);
    cudaGetSymbolAddress((void**)&t2, g_t2);
    cudaGetSymbolAddress((void**)&qkv, g_qkv);
    cudaGetSymbolAddress((void**)&ob, g_ob);
    cudaGetSymbolAddress((void**)&kv, g_kv);
    cudaGetSymbolAddress((void**)&kk, g_k);
    cudaGetSymbolAddress((void**)&vv, g_v);
    cudaGetSymbolAddress((void**)&qq, g_q);
    cudaGetSymbolAddress((void**)&co, g_co);

    const int WSM7 = (3 * 49 * 33 * 3 + 3 * 49 * 49) * 4;   // 87024
    const int WSM4 = (3 * 16 * 33 * 3 + 3 * 16 * 16) * 4;   // 22080
    cudaFuncSetAttribute(win_attn_k<7>, cudaFuncAttributeMaxDynamicSharedMemorySize, WSM7);
    cudaFuncSetAttribute(win_attn_k<4>, cudaFuncAttributeMaxDynamicSharedMemorySize, WSM4);

    // patch merges
    patch_tc<16, 768, 14><<<ROWS0 / 128, 256>>>(x, pw[0], pb[0], t0);
    patch_tc<4, 48, 56><<<ROWS1 / 128, 256>>>(x, pw[1], pb[1], t1);
    patch_tc<7, 147, 32><<<ROWS2 / 128, 256>>>(x, pw[2], pb[2], t2);

    const int rows[3] = {ROWS0, ROWS1, ROWS2};
    float* tb[3] = {t0, t1, t2};
    for (int i = 0; i < 3; ++i) {
        const int R = rows[i];
        float* t = tb[i];
        gemm_tc<float, __half, true, false, 0, false><<<dim3(R / 128, 3), 256>>>(
            t, wa_qkv + i * 96 * 288, nullptr, nullptr,
            wa_ln_g + i * 96, wa_ln_b + i * 96, nullptr, qkv, nullptr, 288);
        if (i == 0)      win_attn_k<7><<<64 * 2 * 2, 128, WSM7>>>(qkv, ob, 14, 2);
        else if (i == 1) win_attn_k<4><<<64 * 14 * 14, 128, WSM4>>>(qkv, ob, 56, 14);
        else             win_attn_k<4><<<64 * 8 * 8, 128, WSM4>>>(qkv, ob, 32, 8);
        gemm_tc<__half, float, false, false, 1, false><<<dim3(R / 128, 1), 256>>>(
            ob, wa_ow + i * 9216, nullptr, wa_ob + i * 96,
            nullptr, nullptr, nullptr, t, nullptr, 96);
        gemm_tc<float, __half, true, true, 0, false><<<dim3(R / 128, 1), 256>>>(
            t, ff_w1 + i * 9216, nullptr, ff_b1 + i * 96,
            ff_ln_g + i * 96, ff_ln_b + i * 96, nullptr, ob, nullptr, 96);
        gemm_tc<__half, float, false, false, 1, false><<<dim3(R / 128, 1), 256>>>(
            ob, ff_w2 + i * 9216, nullptr, ff_b2 + i * 96,
            nullptr, nullptr, nullptr, t, nullptr, 96);
    }

    // neighbor gather + LN -> kv(fp16)
    gather_ln_k<<<64 * 196, 256>>>(t1, t2, lnn_g, lnn_b, kv);
    // k/v projections in one dual launch
    gemm_tc<__half, __half, false, false, 0, true><<<dim3(KVROWS / 128, 2), 256>>>(
        kv, ca_wk, ca_wv, nullptr, nullptr, nullptr, nullptr, kk, vv, 96);
    // q(fp16) = LN(t0) @ Wq
    gemm_tc<float, __half, true, false, 0, false><<<dim3(ROWS0 / 128, 1), 256>>>(
        t0, ca_wq, nullptr, nullptr, lnn_g, lnn_b, nullptr, qq, nullptr, 96);
    // cross attention
    cross_attn_k<<<12544, 128>>>(qq, kk, vv, co);
    // out(fp32) = t0 + co @ Wo + bo
    gemm_tc<__half, float, false, false, 2, false><<<dim3(ROWS0 / 128, 1), 256>>>(
        co, ca_wo, nullptr, ca_bo, nullptr, nullptr, t0, out, nullptr, 96);
    // out += gelu(LN(out) @ w1 + b1) @ w2 + b2
    gemm_tc<float, __half, true, true, 0, false><<<dim3(ROWS0 / 128, 1), 256>>>(
        out, fi_w1, nullptr, fi_b1, fi_ln_g, fi_ln_b, nullptr, ob, nullptr, 96);
    gemm_tc<__half, float, false, false, 1, false><<<dim3(ROWS0 / 128, 1), 256>>>(
        ob, fi_w2, nullptr, fi_b2, nullptr, nullptr, nullptr, out, nullptr, 96);
}